// round 2
// baseline (speedup 1.0000x reference)
#include <cuda_runtime.h>
#include <math.h>

// ---------------------------------------------------------------------------
// unit_gcn fused kernel, fp32 with packed f32x2 FMA.
// Shapes: N=128, C=Cout=64, T=256, V=25, S=3, RED=4, KER=25, PAD=12.
// ---------------------------------------------------------------------------

typedef unsigned long long ull;

__device__ __forceinline__ ull pk2(float lo, float hi) {
    ull r;
    asm("mov.b64 %0, {%1, %2};" : "=l"(r) : "f"(lo), "f"(hi));
    return r;
}
__device__ __forceinline__ void fma2(ull &d, ull a, ull b) {
    asm("fma.rn.f32x2 %0, %1, %2, %0;" : "+l"(d) : "l"(a), "l"(b));
}
__device__ __forceinline__ float2 up2(ull v) {
    float2 r;
    asm("mov.b64 {%0, %1}, %2;" : "=f"(r.x), "=f"(r.y) : "l"(v));
    return r;
}

// ------------------------- device scratch (no allocs) ----------------------
__device__ float d_Afp[3 * 25 * 26];          // Af padded to stride 26 (1950 floats)
__device__ float d_Wc[192 * 64];              // Wc[k=(s,c)][o] = wd[s,o,c]*bn_scale[o]
__device__ float d_Kc[64];                    // per-channel additive const
__device__ float d_pp[32 * 128 * 1600];       // per-(ttile,n) partial T-sums of y
__device__ float d_g[128 * 64 * 25];          // final multiplier (1 + sigmoid)

// ------------------------------- prep --------------------------------------
__global__ void prep_kernel(const float* __restrict__ A, const float* __restrict__ PA,
                            const float* __restrict__ wd, const float* __restrict__ bd,
                            const float* __restrict__ gamma, const float* __restrict__ beta,
                            const float* __restrict__ mean, const float* __restrict__ var)
{
    int tid = threadIdx.x;
    __shared__ float ssc[64];
    if (tid < 64) {
        float sc = gamma[tid] * rsqrtf(var[tid] + 1e-5f);
        ssc[tid] = sc;
        d_Kc[tid] = (bd[tid] + bd[64 + tid] + bd[128 + tid]) * sc
                    + beta[tid] - mean[tid] * sc;
    }
    __syncthreads();
    // Af = A + PA / (||PA[:,w]||_2 + 1e-4), padded row stride 26
    for (int idx = tid; idx < 75; idx += blockDim.x) {
        int s = idx / 25, w = idx % 25;
        float nrm = 0.f;
        for (int v = 0; v < 25; v++) {
            float pv = PA[(s * 25 + v) * 25 + w];
            nrm += pv * pv;
        }
        nrm = sqrtf(nrm) + 1e-4f;
        for (int v = 0; v < 25; v++)
            d_Afp[(s * 25 + v) * 26 + w] =
                A[(s * 25 + v) * 25 + w] + PA[(s * 25 + v) * 25 + w] / nrm;
        d_Afp[idx * 26 + 25] = 0.f;   // pad column (idx spans all 75 (s,v) rows)
    }
    // Wc[k][o] with BN scale folded
    for (int idx = tid; idx < 12288; idx += blockDim.x) {
        int k = idx >> 6, o = idx & 63;
        int s = k >> 6, c = k & 63;
        d_Wc[idx] = wd[(s * 64 + o) * 64 + c] * ssc[o];
    }
}

// ------------------------------- main ---------------------------------------
// One block per (n, 8-frame tile).  320 threads.
// smem: xs[64][201] | Zs[96][201] | Wcs[192*64] | Afs[75*26] | Kcs[64]
#define AFS_FLOATS (3 * 25 * 26)   /* 1950 */
#define SMEM_FLOATS (64*201 + 96*201 + 192*64 + AFS_FLOATS + 64)

__global__ void __launch_bounds__(320, 1)
main_kernel(const float* __restrict__ x, float* __restrict__ out)
{
    extern __shared__ float sm[];
    float* xs  = sm;                   // 12864 floats
    float* Zs  = sm + 64 * 201;        // 19296 floats
    float* Wcs = Zs + 96 * 201;        // 12288 floats
    float* Afs = Wcs + 12288;          // 1950 floats
    float* Kcs = Afs + AFS_FLOATS;     // 64 floats
    float* ps  = Zs;                   // reuse for per-block T-sum (1600)

    const int tid = threadIdx.x;
    const int n   = blockIdx.y;
    const int t0  = blockIdx.x * 8;

    // cooperative loads
    {
        const float* xb = x + (size_t)n * 64 * 6400 + t0 * 25;
        for (int idx = tid; idx < 64 * 200; idx += 320) {
            int c = idx / 200, r = idx - c * 200;
            xs[c * 201 + r] = xb[c * 6400 + r];
        }
        for (int idx = tid; idx < 12288; idx += 320) Wcs[idx] = d_Wc[idx];
        for (int idx = tid; idx < AFS_FLOATS; idx += 320) Afs[idx] = d_Afp[idx];
        if (tid < 64) Kcs[tid] = d_Kc[tid];
    }

    const int m  = tid / 40;         // o-block (8 rows)
    const int nn = tid - m * 40;     // tw-block (5 cols)

    ull yacc[4][5];
    #pragma unroll
    for (int p = 0; p < 4; p++)
        #pragma unroll
        for (int j = 0; j < 5; j++) yacc[p][j] = 0ull;

    for (int chunk = 0; chunk < 2; chunk++) {
        __syncthreads();
        // ---- stage Z: Z[k=(s,c)][t*25+w] = sum_v xs[c][t*25+v] * Af[s][v][w]
        for (int task = tid; task < 768; task += 320) {
            int kl = task % 96;
            int tt = task / 96;
            int kg = chunk * 96 + kl;
            int s = kg >> 6, c = kg & 63;
            const float* xrow = &xs[c * 201 + tt * 25];
            ull zacc[12];
            #pragma unroll
            for (int j = 0; j < 12; j++) zacc[j] = 0ull;
            float z24 = 0.f;
            for (int v = 0; v < 25; v++) {
                float xv = xrow[v];
                ull bx = pk2(xv, xv);
                const ull* ar = (const ull*)&Afs[(s * 25 + v) * 26];
                #pragma unroll
                for (int j = 0; j < 12; j++) fma2(zacc[j], ar[j], bx);
                z24 = fmaf(xv, Afs[(s * 25 + v) * 26 + 24], z24);
            }
            float* zr = &Zs[kl * 201 + tt * 25];
            #pragma unroll
            for (int j = 0; j < 12; j++) {
                float2 t2 = up2(zacc[j]);
                zr[2 * j] = t2.x; zr[2 * j + 1] = t2.y;
            }
            zr[24] = z24;
        }
        __syncthreads();
        // ---- GEMM: Y[o][tw] += Wc[k][o] * Z[k][tw]   (f32x2: o-pairs)
        const float* wb = &Wcs[chunk * 96 * 64 + 8 * m];
        #pragma unroll 2
        for (int k = 0; k < 96; k++) {
            const float* wr = wb + k * 64;
            ulonglong2 A01 = *(const ulonglong2*)(wr);      // {o0,o1},{o2,o3}
            ulonglong2 A23 = *(const ulonglong2*)(wr + 4);  // {o4,o5},{o6,o7}
            const float* zr = &Zs[k * 201 + nn * 5];
            ull b0 = pk2(zr[0], zr[0]);
            ull b1 = pk2(zr[1], zr[1]);
            ull b2 = pk2(zr[2], zr[2]);
            ull b3 = pk2(zr[3], zr[3]);
            ull b4 = pk2(zr[4], zr[4]);
            fma2(yacc[0][0], A01.x, b0); fma2(yacc[0][1], A01.x, b1);
            fma2(yacc[0][2], A01.x, b2); fma2(yacc[0][3], A01.x, b3);
            fma2(yacc[0][4], A01.x, b4);
            fma2(yacc[1][0], A01.y, b0); fma2(yacc[1][1], A01.y, b1);
            fma2(yacc[1][2], A01.y, b2); fma2(yacc[1][3], A01.y, b3);
            fma2(yacc[1][4], A01.y, b4);
            fma2(yacc[2][0], A23.x, b0); fma2(yacc[2][1], A23.x, b1);
            fma2(yacc[2][2], A23.x, b2); fma2(yacc[2][3], A23.x, b3);
            fma2(yacc[2][4], A23.x, b4);
            fma2(yacc[3][0], A23.y, b0); fma2(yacc[3][1], A23.y, b1);
            fma2(yacc[3][2], A23.y, b2); fma2(yacc[3][3], A23.y, b3);
            fma2(yacc[3][4], A23.y, b4);
        }
    }

    __syncthreads();
    for (int idx = tid; idx < 1600; idx += 320) ps[idx] = 0.f;

    // ---- epilogue: BN-const + residual + ReLU
    const int t_idx = nn / 5;
    const int w0 = (nn - t_idx * 5) * 5;
    float yv[4][5][2];
    #pragma unroll
    for (int p = 0; p < 4; p++) {
        int o0 = 8 * m + 2 * p;
        float kc0 = Kcs[o0], kc1 = Kcs[o0 + 1];
        #pragma unroll
        for (int j = 0; j < 5; j++) {
            float2 t2 = up2(yacc[p][j]);
            int tw = t_idx * 25 + w0 + j;
            float r0 = t2.x + kc0 + xs[o0 * 201 + tw];
            float r1 = t2.y + kc1 + xs[(o0 + 1) * 201 + tw];
            yv[p][j][0] = fmaxf(r0, 0.f);
            yv[p][j][1] = fmaxf(r1, 0.f);
        }
    }
    // global stores of y (into d_out; final pass multiplies in place)
    {
        float* ob = out + (size_t)n * 64 * 6400 + (t0 + t_idx) * 25 + w0;
        #pragma unroll
        for (int p = 0; p < 4; p++) {
            int o0 = 8 * m + 2 * p;
            #pragma unroll
            for (int j = 0; j < 5; j++) {
                ob[o0 * 6400 + j]       = yv[p][j][0];
                ob[(o0 + 1) * 6400 + j] = yv[p][j][1];
            }
        }
    }
    // deterministic within-block T-reduction (phase-ordered, no atomics)
    __syncthreads();
    for (int tp = 0; tp < 8; tp++) {
        if (t_idx == tp) {
            #pragma unroll
            for (int p = 0; p < 4; p++) {
                int o0 = 8 * m + 2 * p;
                #pragma unroll
                for (int j = 0; j < 5; j++) {
                    ps[o0 * 25 + w0 + j]       += yv[p][j][0];
                    ps[(o0 + 1) * 25 + w0 + j] += yv[p][j][1];
                }
            }
        }
        __syncthreads();
    }
    float* pout = &d_pp[((size_t)blockIdx.x * 128 + n) * 1600];
    for (int idx = tid; idx < 1600; idx += 320) pout[idx] = ps[idx];
}

// ------------------------------- gate ---------------------------------------
__global__ void gate_kernel(const float* __restrict__ ws, const float* __restrict__ bs,
                            const float* __restrict__ we, const float* __restrict__ be)
{
    __shared__ float p[1600];
    __shared__ float sbuf[100];
    const int n = blockIdx.x, tid = threadIdx.x;   // 128 threads
    // deterministic fixed-order sum over 32 tiles, then T-mean
    for (int idx = tid; idx < 1600; idx += 128) {
        float acc = 0.f;
        for (int tile = 0; tile < 32; tile++)
            acc += d_pp[((size_t)tile * 128 + n) * 1600 + idx];
        p[idx] = acc * (1.0f / 256.0f);
    }
    __syncthreads();
    if (tid < 100) {
        int r = tid / 25, v = tid % 25;
        float acc = bs[r];
        int k0 = 12 - v; if (k0 < 0) k0 = 0;
        int k1 = 36 - v; if (k1 > 24) k1 = 24;
        for (int c = 0; c < 64; c++) {
            const float* wr = &ws[(r * 64 + c) * 25];
            const float* pc = &p[c * 25 + v - 12];
            for (int k = k0; k <= k1; k++)
                acc = fmaf(pc[k], wr[k], acc);
        }
        sbuf[tid] = fmaxf(acc, 0.f);
    }
    __syncthreads();
    for (int idx = tid; idx < 1600; idx += 128) {
        int o = idx / 25, v = idx % 25;
        float z = be[o];
        #pragma unroll
        for (int r = 0; r < 4; r++)
            z = fmaf(sbuf[r * 25 + v], we[o * 4 + r], z);
        d_g[n * 1600 + idx] = 1.f + 1.f / (1.f + expf(-z));
    }
}

// ------------------------------- final --------------------------------------
__global__ void final_kernel(float* __restrict__ out)
{
    unsigned i = blockIdx.x * blockDim.x + threadIdx.x;   // float4 index
    float4 v = reinterpret_cast<float4*>(out)[i];
    unsigned flat = i * 4u;
    unsigned q  = flat / 25u;
    unsigned v0 = flat - q * 25u;
    unsigned co = q / 256u;                                // (n*64+o); constant in a float4
    const float* gr = d_g + (size_t)co * 25u;
    unsigned v1 = v0 + 1u; if (v1 >= 25u) v1 -= 25u;
    unsigned v2 = v0 + 2u; if (v2 >= 25u) v2 -= 25u;
    unsigned v3 = v0 + 3u; if (v3 >= 25u) v3 -= 25u;
    v.x *= gr[v0]; v.y *= gr[v1]; v.z *= gr[v2]; v.w *= gr[v3];
    reinterpret_cast<float4*>(out)[i] = v;
}

// ------------------------------ launcher -------------------------------------
extern "C" void kernel_launch(void* const* d_in, const int* in_sizes, int n_in,
                              void* d_out, int out_size)
{
    const float* x     = (const float*)d_in[0];
    const float* A     = (const float*)d_in[1];
    const float* PA    = (const float*)d_in[2];
    const float* wd    = (const float*)d_in[3];
    const float* bd    = (const float*)d_in[4];
    const float* gamma = (const float*)d_in[5];
    const float* beta  = (const float*)d_in[6];
    const float* mean  = (const float*)d_in[7];
    const float* var   = (const float*)d_in[8];
    const float* sws   = (const float*)d_in[9];
    const float* sbs   = (const float*)d_in[10];
    const float* swe   = (const float*)d_in[11];
    const float* sbe   = (const float*)d_in[12];
    float* out = (float*)d_out;

    const int smem_bytes = SMEM_FLOATS * (int)sizeof(float);  // 185848
    cudaFuncSetAttribute(main_kernel, cudaFuncAttributeMaxDynamicSharedMemorySize,
                         smem_bytes);

    prep_kernel<<<1, 256>>>(A, PA, wd, bd, gamma, beta, mean, var);
    dim3 grid(32, 128);
    main_kernel<<<grid, 320, smem_bytes>>>(x, out);
    gate_kernel<<<128, 128>>>(sws, sbs, swe, sbe);
    final_kernel<<<51200, 256>>>(out);
}

// round 3
// speedup vs baseline: 1.0711x; 1.0711x over previous
#include <cuda_runtime.h>
#include <math.h>

// ---------------------------------------------------------------------------
// unit_gcn fused kernel, fp32 with packed f32x2 FMA.  W-first ordering:
//   P_s = (BN-folded Wd_s) @ X   (64x64 @ 64x200 per 8-frame tile)
//   Y  += sum_v P_s[o][t,v] * Af_s[v][w]
// Shapes: N=128, C=Cout=64, T=256, V=25, S=3, RED=4, KER=25, PAD=12.
// ---------------------------------------------------------------------------

typedef unsigned long long ull;

__device__ __forceinline__ ull pk2(float lo, float hi) {
    ull r;
    asm("mov.b64 %0, {%1, %2};" : "=l"(r) : "f"(lo), "f"(hi));
    return r;
}
__device__ __forceinline__ void fma2(ull &d, ull a, ull b) {
    asm("fma.rn.f32x2 %0, %1, %2, %0;" : "+l"(d) : "l"(a), "l"(b));
}
__device__ __forceinline__ float2 up2(ull v) {
    float2 r;
    asm("mov.b64 {%0, %1}, %2;" : "=f"(r.x), "=f"(r.y) : "l"(v));
    return r;
}

// ------------------------- device scratch (no allocs) ----------------------
__device__ float d_Afp[3 * 25 * 26];          // Af padded to stride 26 (1950 floats)
__device__ float d_Wc[192 * 64];              // d_Wc[(s*64+c)*64 + o] = wd[s,o,c]*bn_scale[o]
__device__ float d_Kc[64];                    // per-channel additive const
__device__ float d_pp[32 * 128 * 1600];       // per-(ttile,n) partial T-sums of y
__device__ float d_g[128 * 64 * 25];          // final multiplier (1 + sigmoid)

// ------------------------------- prep --------------------------------------
__global__ void prep_kernel(const float* __restrict__ A, const float* __restrict__ PA,
                            const float* __restrict__ wd, const float* __restrict__ bd,
                            const float* __restrict__ gamma, const float* __restrict__ beta,
                            const float* __restrict__ mean, const float* __restrict__ var)
{
    int tid = threadIdx.x;
    __shared__ float ssc[64];
    if (tid < 64) {
        float sc = gamma[tid] * rsqrtf(var[tid] + 1e-5f);
        ssc[tid] = sc;
        d_Kc[tid] = (bd[tid] + bd[64 + tid] + bd[128 + tid]) * sc
                    + beta[tid] - mean[tid] * sc;
    }
    __syncthreads();
    // Af = A + PA / (||PA[:,w]||_2 + 1e-4), padded row stride 26
    for (int idx = tid; idx < 75; idx += blockDim.x) {
        int s = idx / 25, w = idx % 25;
        float nrm = 0.f;
        for (int v = 0; v < 25; v++) {
            float pv = PA[(s * 25 + v) * 25 + w];
            nrm += pv * pv;
        }
        nrm = sqrtf(nrm) + 1e-4f;
        for (int v = 0; v < 25; v++)
            d_Afp[(s * 25 + v) * 26 + w] =
                A[(s * 25 + v) * 25 + w] + PA[(s * 25 + v) * 25 + w] / nrm;
        d_Afp[idx * 26 + 25] = 0.f;
    }
    // Wc[(s,c)][o] with BN scale folded
    for (int idx = tid; idx < 12288; idx += blockDim.x) {
        int k = idx >> 6, o = idx & 63;
        int s = k >> 6, c = k & 63;
        d_Wc[idx] = wd[(s * 64 + o) * 64 + c] * ssc[o];
    }
}

// ------------------------------- main ---------------------------------------
// One block per (n, 8-frame tile).  320 threads.
// smem: xs[64][201] | Ps[64][201] | Wcs[192*64] | Afs[75*26] | Kcs[64]
#define AFS_FLOATS (3 * 25 * 26)   /* 1950 */
#define SMEM_FLOATS (64*201 + 64*201 + 192*64 + AFS_FLOATS + 64)

__global__ void __launch_bounds__(320, 1)
main_kernel(const float* __restrict__ x, float* __restrict__ out)
{
    extern __shared__ float sm[];
    float* xs  = sm;                   // 12864 floats
    float* Ps  = sm + 64 * 201;        // 12864 floats
    float* Wcs = Ps + 64 * 201;        // 12288 floats
    float* Afs = Wcs + 12288;          // 1950 floats
    float* Kcs = Afs + AFS_FLOATS;     // 64 floats
    float* ps  = Ps;                   // reuse for per-block T-sum (1600)

    const int tid = threadIdx.x;
    const int n   = blockIdx.y;
    const int t0  = blockIdx.x * 8;

    // cooperative loads
    {
        const float* xb = x + (size_t)n * 64 * 6400 + t0 * 25;
        for (int idx = tid; idx < 64 * 200; idx += 320) {
            int c = idx / 200, r = idx - c * 200;
            xs[c * 201 + r] = xb[c * 6400 + r];
        }
        for (int idx = tid; idx < 12288; idx += 320) Wcs[idx] = d_Wc[idx];
        for (int idx = tid; idx < AFS_FLOATS; idx += 320) Afs[idx] = d_Afp[idx];
        if (tid < 64) Kcs[tid] = d_Kc[tid];
    }
    __syncthreads();

    const int m     = tid / 40;          // o-block (8 rows: o = 8m..8m+7)
    const int nn    = tid - m * 40;      // tw-block (5 cols)
    const int t_idx = nn / 5;            // frame within tile (0..7)
    const int w0    = (nn - t_idx * 5) * 5;
    const int col0  = t_idx * 25 + w0;   // output column base (tw)

    ull yacc[4][5];
    #pragma unroll
    for (int p = 0; p < 4; p++)
        #pragma unroll
        for (int j = 0; j < 5; j++) yacc[p][j] = 0ull;

    for (int s = 0; s < 3; s++) {
        // ---- stage 1: P = Wd_s @ X  (per-thread 8o x 5tv f32x2 tile) ----
        ull pacc[4][5];
        #pragma unroll
        for (int p = 0; p < 4; p++)
            #pragma unroll
            for (int j = 0; j < 5; j++) pacc[p][j] = 0ull;

        #pragma unroll 2
        for (int c = 0; c < 64; c++) {
            const float* wr = &Wcs[((s * 64 + c) << 6) + 8 * m];
            ulonglong2 A01 = *(const ulonglong2*)(wr);      // {o0,o1},{o2,o3}
            ulonglong2 A23 = *(const ulonglong2*)(wr + 4);  // {o4,o5},{o6,o7}
            const float* zr = &xs[c * 201 + nn * 5];
            ull b0 = pk2(zr[0], zr[0]);
            ull b1 = pk2(zr[1], zr[1]);
            ull b2 = pk2(zr[2], zr[2]);
            ull b3 = pk2(zr[3], zr[3]);
            ull b4 = pk2(zr[4], zr[4]);
            fma2(pacc[0][0], A01.x, b0); fma2(pacc[0][1], A01.x, b1);
            fma2(pacc[0][2], A01.x, b2); fma2(pacc[0][3], A01.x, b3);
            fma2(pacc[0][4], A01.x, b4);
            fma2(pacc[1][0], A01.y, b0); fma2(pacc[1][1], A01.y, b1);
            fma2(pacc[1][2], A01.y, b2); fma2(pacc[1][3], A01.y, b3);
            fma2(pacc[1][4], A01.y, b4);
            fma2(pacc[2][0], A23.x, b0); fma2(pacc[2][1], A23.x, b1);
            fma2(pacc[2][2], A23.x, b2); fma2(pacc[2][3], A23.x, b3);
            fma2(pacc[2][4], A23.x, b4);
            fma2(pacc[3][0], A23.y, b0); fma2(pacc[3][1], A23.y, b1);
            fma2(pacc[3][2], A23.y, b2); fma2(pacc[3][3], A23.y, b3);
            fma2(pacc[3][4], A23.y, b4);
        }

        __syncthreads();   // previous stage-2 readers of Ps are done
        #pragma unroll
        for (int p = 0; p < 4; p++) {
            int o0 = 8 * m + 2 * p;
            #pragma unroll
            for (int j = 0; j < 5; j++) {
                float2 t2 = up2(pacc[p][j]);
                Ps[o0 * 201 + col0 + j]       = t2.x;
                Ps[(o0 + 1) * 201 + col0 + j] = t2.y;
            }
        }
        __syncthreads();   // Ps ready

        // ---- stage 2: yacc += sum_v P[o][t,v] * Af_s[v][w] ----
        #pragma unroll 5
        for (int v = 0; v < 25; v++) {
            const float* afr = &Afs[(s * 25 + v) * 26 + w0];
            ull a0 = pk2(afr[0], afr[0]);
            ull a1 = pk2(afr[1], afr[1]);
            ull a2 = pk2(afr[2], afr[2]);
            ull a3 = pk2(afr[3], afr[3]);
            ull a4 = pk2(afr[4], afr[4]);
            const int pcol = t_idx * 25 + v;
            #pragma unroll
            for (int p = 0; p < 4; p++) {
                int o0 = 8 * m + 2 * p;
                ull pv = pk2(Ps[o0 * 201 + pcol], Ps[(o0 + 1) * 201 + pcol]);
                fma2(yacc[p][0], pv, a0);
                fma2(yacc[p][1], pv, a1);
                fma2(yacc[p][2], pv, a2);
                fma2(yacc[p][3], pv, a3);
                fma2(yacc[p][4], pv, a4);
            }
        }
    }

    __syncthreads();
    for (int idx = tid; idx < 1600; idx += 320) ps[idx] = 0.f;

    // ---- epilogue: BN-const + residual + ReLU
    float yv[4][5][2];
    #pragma unroll
    for (int p = 0; p < 4; p++) {
        int o0 = 8 * m + 2 * p;
        float kc0 = Kcs[o0], kc1 = Kcs[o0 + 1];
        #pragma unroll
        for (int j = 0; j < 5; j++) {
            float2 t2 = up2(yacc[p][j]);
            float r0 = t2.x + kc0 + xs[o0 * 201 + col0 + j];
            float r1 = t2.y + kc1 + xs[(o0 + 1) * 201 + col0 + j];
            yv[p][j][0] = fmaxf(r0, 0.f);
            yv[p][j][1] = fmaxf(r1, 0.f);
        }
    }
    // global stores of y (into d_out; final pass multiplies in place)
    {
        float* ob = out + (size_t)n * 64 * 6400 + (t0 + t_idx) * 25 + w0;
        #pragma unroll
        for (int p = 0; p < 4; p++) {
            int o0 = 8 * m + 2 * p;
            #pragma unroll
            for (int j = 0; j < 5; j++) {
                ob[o0 * 6400 + j]       = yv[p][j][0];
                ob[(o0 + 1) * 6400 + j] = yv[p][j][1];
            }
        }
    }
    // deterministic within-block T-reduction (phase-ordered, no atomics)
    __syncthreads();
    for (int tp = 0; tp < 8; tp++) {
        if (t_idx == tp) {
            #pragma unroll
            for (int p = 0; p < 4; p++) {
                int o0 = 8 * m + 2 * p;
                #pragma unroll
                for (int j = 0; j < 5; j++) {
                    ps[o0 * 25 + w0 + j]       += yv[p][j][0];
                    ps[(o0 + 1) * 25 + w0 + j] += yv[p][j][1];
                }
            }
        }
        __syncthreads();
    }
    float* pout = &d_pp[((size_t)blockIdx.x * 128 + n) * 1600];
    for (int idx = tid; idx < 1600; idx += 320) pout[idx] = ps[idx];
}

// ------------------------------- gate ---------------------------------------
__global__ void gate_kernel(const float* __restrict__ ws, const float* __restrict__ bs,
                            const float* __restrict__ we, const float* __restrict__ be)
{
    __shared__ float p[1600];
    __shared__ float sbuf[100];
    const int n = blockIdx.x, tid = threadIdx.x;   // 128 threads
    for (int idx = tid; idx < 1600; idx += 128) {
        float acc = 0.f;
        for (int tile = 0; tile < 32; tile++)
            acc += d_pp[((size_t)tile * 128 + n) * 1600 + idx];
        p[idx] = acc * (1.0f / 256.0f);
    }
    __syncthreads();
    if (tid < 100) {
        int r = tid / 25, v = tid % 25;
        float acc = bs[r];
        int k0 = 12 - v; if (k0 < 0) k0 = 0;
        int k1 = 36 - v; if (k1 > 24) k1 = 24;
        for (int c = 0; c < 64; c++) {
            const float* wr = &ws[(r * 64 + c) * 25];
            const float* pc = &p[c * 25 + v - 12];
            for (int k = k0; k <= k1; k++)
                acc = fmaf(pc[k], wr[k], acc);
        }
        sbuf[tid] = fmaxf(acc, 0.f);
    }
    __syncthreads();
    for (int idx = tid; idx < 1600; idx += 128) {
        int o = idx / 25, v = idx % 25;
        float z = be[o];
        #pragma unroll
        for (int r = 0; r < 4; r++)
            z = fmaf(sbuf[r * 25 + v], we[o * 4 + r], z);
        d_g[n * 1600 + idx] = 1.f + 1.f / (1.f + expf(-z));
    }
}

// ------------------------------- final --------------------------------------
__global__ void final_kernel(float* __restrict__ out)
{
    unsigned i = blockIdx.x * blockDim.x + threadIdx.x;   // float4 index
    float4 v = reinterpret_cast<float4*>(out)[i];
    unsigned flat = i * 4u;
    unsigned q  = flat / 25u;
    unsigned v0 = flat - q * 25u;
    unsigned co = q / 256u;                                // (n*64+o); constant in a float4
    const float* gr = d_g + (size_t)co * 25u;
    unsigned v1 = v0 + 1u; if (v1 >= 25u) v1 -= 25u;
    unsigned v2 = v0 + 2u; if (v2 >= 25u) v2 -= 25u;
    unsigned v3 = v0 + 3u; if (v3 >= 25u) v3 -= 25u;
    v.x *= gr[v0]; v.y *= gr[v1]; v.z *= gr[v2]; v.w *= gr[v3];
    reinterpret_cast<float4*>(out)[i] = v;
}

// ------------------------------ launcher -------------------------------------
extern "C" void kernel_launch(void* const* d_in, const int* in_sizes, int n_in,
                              void* d_out, int out_size)
{
    const float* x     = (const float*)d_in[0];
    const float* A     = (const float*)d_in[1];
    const float* PA    = (const float*)d_in[2];
    const float* wd    = (const float*)d_in[3];
    const float* bd    = (const float*)d_in[4];
    const float* gamma = (const float*)d_in[5];
    const float* beta  = (const float*)d_in[6];
    const float* mean  = (const float*)d_in[7];
    const float* var   = (const float*)d_in[8];
    const float* sws   = (const float*)d_in[9];
    const float* sbs   = (const float*)d_in[10];
    const float* swe   = (const float*)d_in[11];
    const float* sbe   = (const float*)d_in[12];
    float* out = (float*)d_out;

    const int smem_bytes = SMEM_FLOATS * (int)sizeof(float);  // 160120
    cudaFuncSetAttribute(main_kernel, cudaFuncAttributeMaxDynamicSharedMemorySize,
                         smem_bytes);

    prep_kernel<<<1, 256>>>(A, PA, wd, bd, gamma, beta, mean, var);
    dim3 grid(32, 128);
    main_kernel<<<grid, 320, smem_bytes>>>(x, out);
    gate_kernel<<<128, 128>>>(sws, sbs, swe, sbe);
    final_kernel<<<51200, 256>>>(out);
}